// round 15
// baseline (speedup 1.0000x reference)
#include <cuda_runtime.h>

// Problem constants (fixed shapes per reference)
#define BB   16
#define NN   1024
#define D2H  1024
#define UU   512
#define BN   (BB * NN)      // 16384 rows

#define FCH     4           // fold u-chunks (UU/FCH = 128 u per chunk)
#define GRID2   512         // fused kernel grid — MUST be all-resident
#define ROWS_PB 32          // rows per fused block (512*32 = 16384)
#define BLK_PB  (NN / ROWS_PB)   // 32 blocks per batch

// Scratch (device globals; no allocation allowed)
__device__ float    g_part[FCH * 2 * D2H];  // partial v_h/v_m per u-chunk (32 KB)
__device__ float    g_c[2];                 // c_h + b_out, c_m
__device__ float    g_sM[BN];               // modifier scores (cross-block)
__device__ unsigned g_cnt[BB];              // per-batch completion counters

// ---------------------------------------------------------------------------
// Kernel 1: partial fold, wide. Grid 128 = 4 u-chunks x 32 d-groups, 256 thr.
// Block (uc,dg): d in [dg*32, dg*32+32) (lane), u in [uc*128, uc*128+128)
// (warp*16 each). 16+16 coalesced loads/thread -> ~3us for 4 MB.
// Also zeroes the per-batch counters (graph-replay idempotent) and computes
// the bias constants.
// ---------------------------------------------------------------------------
__global__ void fold_part_kernel(const float* __restrict__ W_h,
                                 const float* __restrict__ b_h,
                                 const float* __restrict__ W_m,
                                 const float* __restrict__ b_m,
                                 const float* __restrict__ w_out,
                                 const float* __restrict__ b_out) {
    __shared__ float sw[128];
    __shared__ float ph[8][32], pm[8][32];
    int tid = threadIdx.x, warp = tid >> 5, lane = tid & 31;
    int uc = blockIdx.x >> 5;            // u-chunk   0..3
    int dg = blockIdx.x & 31;            // d-group   0..31
    int u0 = uc * 128;

    if (tid < 128) sw[tid] = w_out[u0 + tid];
    if (blockIdx.x == 0 && tid < BB) g_cnt[tid] = 0;   // reset batch barriers
    __syncthreads();

    int d = dg * 32 + lane;
    float vh = 0.f, vm = 0.f;
#pragma unroll
    for (int k = 0; k < 16; k++) {
        int u = u0 + warp * 16 + k;
        float w = sw[warp * 16 + k];
        vh = fmaf(W_h[u * D2H + d], w, vh);
        vm = fmaf(W_m[u * D2H + d], w, vm);
    }
    ph[warp][lane] = vh;
    pm[warp][lane] = vm;
    __syncthreads();

    if (warp == 0) {
        float a = 0.f;
#pragma unroll
        for (int w = 0; w < 8; w++) a += ph[w][lane];
        g_part[uc * 2 * D2H + d] = a;
    } else if (warp == 1) {
        float a = 0.f;
#pragma unroll
        for (int w = 0; w < 8; w++) a += pm[w][lane];
        g_part[uc * 2 * D2H + D2H + d] = a;
    } else if (blockIdx.x == 0 && warp == 2) {
        float ch = 0.f, cm = 0.f;
        for (int u = lane; u < UU; u += 32) {
            float w = w_out[u];
            ch = fmaf(b_h[u], w, ch);
            cm = fmaf(b_m[u], w, cm);
        }
#pragma unroll
        for (int o = 16; o > 0; o >>= 1) {
            ch += __shfl_down_sync(0xffffffffu, ch, o);
            cm += __shfl_down_sync(0xffffffffu, cm, o);
        }
        if (lane == 0) {
            g_c[0] = ch + b_out[0];
            g_c[1] = cm;
        }
    }
}

// ---------------------------------------------------------------------------
// Kernel 2: persistent fused reduce + dots + PER-BATCH sync + bcast.
// Grid 512 x 256, __launch_bounds__(256,4): all blocks wave-1 resident
// (512 <= 148*4), so a per-batch barrier (32 sibling blocks) is deadlock-free.
// A block only waits for its own batch's 32 producers -> early batches start
// Phase-B writes while late batches still run Phase-A reads (HBM r/w overlap,
// skew cost = batch-max not global-max).
//  Phase 0: reduce 4-chunk partials into smem sv (v_h|v_m).
//  Phase A: dots for 32 rows (4/warp); sH -> smem, sM -> global (released).
//  sync:    per-batch atomicAdd + spin to BLK_PB.
//  Phase B: out[b,i,j] = sH[i] + sM[b,j], 32 rows, streaming stores.
// ---------------------------------------------------------------------------
__global__ void __launch_bounds__(256, 4)
fused_kernel(const float* __restrict__ x, float* __restrict__ out) {
    __shared__ float4 sv[2 * D2H / 4];   // 8 KB: v_h then v_m
    __shared__ float  ssH[ROWS_PB];
    int tid = threadIdx.x, warp = tid >> 5, lane = tid & 31;

    // Phase 0: reduce partials (g_part stays in L2: 32 KB)
    const float4* gp4 = (const float4*)g_part;
#pragma unroll
    for (int i = tid; i < 512; i += 256) {
        float4 a = gp4[i], b = gp4[512 + i], c = gp4[1024 + i], d = gp4[1536 + i];
        sv[i] = make_float4(a.x + b.x + c.x + d.x, a.y + b.y + c.y + d.y,
                            a.z + b.z + c.z + d.z, a.w + b.w + c.w + d.w);
    }
    __syncthreads();

    // Phase A: dots, 4 rows per warp
    int row0 = blockIdx.x * ROWS_PB + warp * 4;
    const float4* xr = (const float4*)(x + (size_t)row0 * D2H);
    float ah[4] = {0,0,0,0}, am[4] = {0,0,0,0};
#pragma unroll
    for (int k = 0; k < 8; k++) {
        int i = k * 32 + lane;           // 256 float4 per row, coalesced
        float4 h = sv[i], m = sv[256 + i];
#pragma unroll
        for (int r = 0; r < 4; r++) {
            float4 v = xr[r * (D2H / 4) + i];
            ah[r] = fmaf(v.x, h.x, fmaf(v.y, h.y, fmaf(v.z, h.z, fmaf(v.w, h.w, ah[r]))));
            am[r] = fmaf(v.x, m.x, fmaf(v.y, m.y, fmaf(v.z, m.z, fmaf(v.w, m.w, am[r]))));
        }
    }
#pragma unroll
    for (int o = 16; o > 0; o >>= 1) {
#pragma unroll
        for (int r = 0; r < 4; r++) {
            ah[r] += __shfl_down_sync(0xffffffffu, ah[r], o);
            am[r] += __shfl_down_sync(0xffffffffu, am[r], o);
        }
    }
    if (lane == 0) {
        float ch = g_c[0], cm = g_c[1];
#pragma unroll
        for (int r = 0; r < 4; r++) {
            ssH[warp * 4 + r] = ah[r] + ch;   // block-local
            g_sM[row0 + r]    = am[r] + cm;   // cross-block
        }
        __threadfence();                      // release sM
    }
    __syncthreads();

    // Per-batch barrier: wait only for this batch's 32 producer blocks.
    int b = blockIdx.x / BLK_PB;              // batch index
    if (tid == 0) {
        atomicAdd(&g_cnt[b], 1u);
        volatile unsigned* p = &g_cnt[b];
        while (*p < BLK_PB) __nanosleep(32);
    }
    __syncthreads();
    __threadfence();                          // acquire published sM

    // Phase B: broadcast-add this block's 32 rows (all same batch: 32|1024)
    int bi0 = blockIdx.x * ROWS_PB;
    const float4* m4 = (const float4*)g_sM + b * (NN / 4);
    float4 m = m4[tid];

    float4* o4 = (float4*)out + (size_t)bi0 * (NN / 4) + tid;
#pragma unroll 4
    for (int r = 0; r < ROWS_PB; r++) {
        float s = ssH[r];
        __stcs(&o4[r * (NN / 4)],
               make_float4(s + m.x, s + m.y, s + m.z, s + m.w));
    }
}

// ---------------------------------------------------------------------------
extern "C" void kernel_launch(void* const* d_in, const int* in_sizes, int n_in,
                              void* d_out, int out_size) {
    const float* x     = (const float*)d_in[0];
    const float* W_h   = (const float*)d_in[1];
    const float* b_h   = (const float*)d_in[2];
    const float* W_m   = (const float*)d_in[3];
    const float* b_m   = (const float*)d_in[4];
    const float* w_out = (const float*)d_in[5];
    const float* b_out = (const float*)d_in[6];
    float* out = (float*)d_out;

    fold_part_kernel<<<32 * FCH, 256>>>(W_h, b_h, W_m, b_m, w_out, b_out);
    fused_kernel<<<GRID2, 256>>>(x, out);
}

// round 16
// speedup vs baseline: 1.1640x; 1.1640x over previous
#include <cuda_runtime.h>

// Problem constants (fixed shapes per reference)
#define BB   16
#define NN   1024
#define D2H  1024
#define UU   512
#define BN   (BB * NN)      // 16384 rows

#define FCH     4           // fold u-chunks (UU/FCH = 128 u per chunk)
#define GRID2   512u        // grid — MUST be all-resident (512 <= 148*4)
#define ROWS_PB 32          // rows per block (512*32 = 16384)
#define BLK_PB  32u         // blocks per batch (NN / ROWS_PB)

// Scratch (device globals; no allocation allowed)
__device__ float    g_part[FCH * 2 * D2H];  // partial v_h/v_m per u-chunk (32 KB)
__device__ float    g_c[2];                 // c_h + b_out, c_m
__device__ float    g_sM[BN];               // modifier scores (cross-block)
__device__ unsigned g_bar0;                 // global ticket barrier (monotonic)
__device__ unsigned g_barB[BB];             // per-batch ticket barriers (monotonic)

// Monotonic ticket barrier: never reset, replay-safe. Each use consumes
// exactly `width` increments; waiter's target is the end of its own epoch.
__device__ __forceinline__ void ticket_barrier(unsigned* cnt, unsigned width) {
    unsigned t = atomicAdd(cnt, 1u);
    unsigned target = (t / width + 1u) * width;
    volatile unsigned* p = cnt;
    while (*p < target) __nanosleep(32);
}

// ---------------------------------------------------------------------------
// ONE persistent kernel, 512 blocks x 256 threads, all wave-1 resident.
//  Phase F (blocks 0..127): wide partial fold of W_h/W_m with w_out into
//           g_part (4 u-chunks x 32 d-groups; 16+16 coalesced loads/thread).
//           Block 0 also computes the bias constants.
//  Barrier 0 (global ticket): fold results visible to everyone.
//  Phase 0: every block reduces the 4 chunk partials (32 KB, L2) into smem.
//  Phase A: dots for its 32 rows (4 per warp, 32 float4 loads in flight per
//           lane); sH -> smem, sM -> global (release fence).
//  Barrier b (per-batch ticket): only this batch's 32 producers.
//  Phase B: out[b,i,j] = sH[i] + sM[b,j], streaming stores.
// ---------------------------------------------------------------------------
__global__ void __launch_bounds__(256, 4)
fused_all_kernel(const float* __restrict__ x,
                 const float* __restrict__ W_h,
                 const float* __restrict__ b_h,
                 const float* __restrict__ W_m,
                 const float* __restrict__ b_m,
                 const float* __restrict__ w_out,
                 const float* __restrict__ b_out,
                 float* __restrict__ out) {
    __shared__ float4 sv[2 * D2H / 4];   // 8 KB: v_h then v_m
    __shared__ float  ssH[ROWS_PB];
    __shared__ float  ph[8][32], pm[8][32];
    __shared__ float  sw[128];
    int tid = threadIdx.x, warp = tid >> 5, lane = tid & 31;

    // ---- Phase F: fold (first 128 blocks only) ----
    if (blockIdx.x < 32 * FCH) {
        int uc = blockIdx.x >> 5;        // u-chunk 0..3
        int dg = blockIdx.x & 31;        // d-group 0..31
        int u0 = uc * 128;

        if (tid < 128) sw[tid] = w_out[u0 + tid];
        __syncthreads();

        int d = dg * 32 + lane;
        float vh = 0.f, vm = 0.f;
#pragma unroll
        for (int k = 0; k < 16; k++) {
            int u = u0 + warp * 16 + k;
            float w = sw[warp * 16 + k];
            vh = fmaf(W_h[u * D2H + d], w, vh);
            vm = fmaf(W_m[u * D2H + d], w, vm);
        }
        ph[warp][lane] = vh;
        pm[warp][lane] = vm;
        __syncthreads();

        if (warp == 0) {
            float a = 0.f;
#pragma unroll
            for (int w = 0; w < 8; w++) a += ph[w][lane];
            g_part[uc * 2 * D2H + d] = a;
        } else if (warp == 1) {
            float a = 0.f;
#pragma unroll
            for (int w = 0; w < 8; w++) a += pm[w][lane];
            g_part[uc * 2 * D2H + D2H + d] = a;
        } else if (blockIdx.x == 0 && warp == 2) {
            float ch = 0.f, cm = 0.f;
            for (int u = lane; u < UU; u += 32) {
                float w = w_out[u];
                ch = fmaf(b_h[u], w, ch);
                cm = fmaf(b_m[u], w, cm);
            }
#pragma unroll
            for (int o = 16; o > 0; o >>= 1) {
                ch += __shfl_down_sync(0xffffffffu, ch, o);
                cm += __shfl_down_sync(0xffffffffu, cm, o);
            }
            if (lane == 0) {
                g_c[0] = ch + b_out[0];
                g_c[1] = cm;
            }
        }
        __syncthreads();
        if (tid == 0) __threadfence();   // release g_part / g_c
    }

    // ---- Barrier 0: global (all 512 resident -> deadlock-free) ----
    __syncthreads();
    if (tid == 0) ticket_barrier(&g_bar0, GRID2);
    __syncthreads();
    __threadfence();                     // acquire g_part / g_c

    // ---- Phase 0: reduce partials into smem (g_part is L2-hot, 32 KB) ----
    const float4* gp4 = (const float4*)g_part;
#pragma unroll
    for (int i = tid; i < 512; i += 256) {
        float4 a = gp4[i], b = gp4[512 + i], c = gp4[1024 + i], d = gp4[1536 + i];
        sv[i] = make_float4(a.x + b.x + c.x + d.x, a.y + b.y + c.y + d.y,
                            a.z + b.z + c.z + d.z, a.w + b.w + c.w + d.w);
    }
    __syncthreads();

    // ---- Phase A: dots, 4 rows per warp ----
    int row0 = blockIdx.x * ROWS_PB + warp * 4;
    const float4* xr = (const float4*)(x + (size_t)row0 * D2H);
    float ah[4] = {0,0,0,0}, am[4] = {0,0,0,0};
#pragma unroll
    for (int k = 0; k < 8; k++) {
        int i = k * 32 + lane;           // 256 float4 per row, coalesced
        float4 h = sv[i], m = sv[256 + i];
#pragma unroll
        for (int r = 0; r < 4; r++) {
            float4 v = xr[r * (D2H / 4) + i];
            ah[r] = fmaf(v.x, h.x, fmaf(v.y, h.y, fmaf(v.z, h.z, fmaf(v.w, h.w, ah[r]))));
            am[r] = fmaf(v.x, m.x, fmaf(v.y, m.y, fmaf(v.z, m.z, fmaf(v.w, m.w, am[r]))));
        }
    }
#pragma unroll
    for (int o = 16; o > 0; o >>= 1) {
#pragma unroll
        for (int r = 0; r < 4; r++) {
            ah[r] += __shfl_down_sync(0xffffffffu, ah[r], o);
            am[r] += __shfl_down_sync(0xffffffffu, am[r], o);
        }
    }
    if (lane == 0) {
        float ch = g_c[0], cm = g_c[1];
#pragma unroll
        for (int r = 0; r < 4; r++) {
            ssH[warp * 4 + r] = ah[r] + ch;   // block-local
            g_sM[row0 + r]    = am[r] + cm;   // cross-block
        }
        __threadfence();                      // release sM
    }
    __syncthreads();

    // ---- Barrier b: per-batch (32 sibling blocks) ----
    unsigned b = blockIdx.x / BLK_PB;
    if (tid == 0) ticket_barrier(&g_barB[b], BLK_PB);
    __syncthreads();
    __threadfence();                          // acquire published sM

    // ---- Phase B: broadcast-add this block's 32 rows ----
    int bi0 = blockIdx.x * ROWS_PB;
    const float4* m4 = (const float4*)g_sM + b * (NN / 4);
    float4 m = m4[tid];

    float4* o4 = (float4*)out + (size_t)bi0 * (NN / 4) + tid;
#pragma unroll 4
    for (int r = 0; r < ROWS_PB; r++) {
        float s = ssH[r];
        __stcs(&o4[r * (NN / 4)],
               make_float4(s + m.x, s + m.y, s + m.z, s + m.w));
    }
}

// ---------------------------------------------------------------------------
extern "C" void kernel_launch(void* const* d_in, const int* in_sizes, int n_in,
                              void* d_out, int out_size) {
    const float* x     = (const float*)d_in[0];
    const float* W_h   = (const float*)d_in[1];
    const float* b_h   = (const float*)d_in[2];
    const float* W_m   = (const float*)d_in[3];
    const float* b_m   = (const float*)d_in[4];
    const float* w_out = (const float*)d_in[5];
    const float* b_out = (const float*)d_in[6];
    float* out = (float*)d_out;

    fused_all_kernel<<<GRID2, 256>>>(x, W_h, b_h, W_m, b_m, w_out, b_out, out);
}